// round 13
// baseline (speedup 1.0000x reference)
#include <cuda_runtime.h>
#include <cuda_bf16.h>
#include <cstdint>

// Problem dims (fixed)
#define T_SEQ     2048
#define D_MODEL   2048
#define NH        16
#define CONV_DIM  6144
#define GEN_HIDDEN 768
#define KERN_N    (CONV_DIM*4)   // 24576

// ---------------- scratch (static __device__, no allocation) ----------------
__device__ float g_qkv [(size_t)T_SEQ*CONV_DIM];
__device__ float g_u   [(size_t)T_SEQ*CONV_DIM];
__device__ float g_beta [T_SEQ*NH];
__device__ float g_decay[T_SEQ*NH];
__device__ float g_qs   [T_SEQ*NH];
__device__ float g_ks   [T_SEQ*NH];
__device__ float g_qk   [T_SEQ*NH];

// bf16 hi/lo split activations
__device__ __nv_bfloat16 g_xh  [(size_t)T_SEQ*D_MODEL],   g_xl  [(size_t)T_SEQ*D_MODEL];
__device__ __nv_bfloat16 g_qkvh[(size_t)T_SEQ*CONV_DIM],  g_qkvl[(size_t)T_SEQ*CONV_DIM];
__device__ __nv_bfloat16 g_hh  [(size_t)T_SEQ*GEN_HIDDEN],g_hl  [(size_t)T_SEQ*GEN_HIDDEN];
__device__ __nv_bfloat16 g_oh  [(size_t)T_SEQ*D_MODEL],   g_ol  [(size_t)T_SEQ*D_MODEL];
// bf16 hi/lo split transposed weights ([N,K] K-major)
__device__ __nv_bfloat16 g_wqkvh[(size_t)CONV_DIM*D_MODEL], g_wqkvl[(size_t)CONV_DIM*D_MODEL];
__device__ __nv_bfloat16 g_w1h [(size_t)GEN_HIDDEN*CONV_DIM], g_w1l [(size_t)GEN_HIDDEN*CONV_DIM];
__device__ __nv_bfloat16 g_w2h [(size_t)KERN_N*GEN_HIDDEN],  g_w2l [(size_t)KERN_N*GEN_HIDDEN];
__device__ __nv_bfloat16 g_woh [(size_t)D_MODEL*D_MODEL],    g_wol [(size_t)D_MODEL*D_MODEL];

__device__ __forceinline__ float siluf(float x){ return x / (1.0f + expf(-x)); }

// ---------------- PTX helpers (baseline ISA only: sm_80-level) --------------
__device__ __forceinline__ uint32_t smem_u32(const void* p){
    return (uint32_t)__cvta_generic_to_shared(p);
}
__device__ __forceinline__ void cpa16(uint32_t d, const void* g){
    asm volatile("cp.async.cg.shared.global [%0], [%1], 16;" :: "r"(d), "l"(g));
}
__device__ __forceinline__ void cpa4(const void* s, const void* g){
    asm volatile("cp.async.ca.shared.global [%0], [%1], 4;" :: "r"(smem_u32(s)), "l"(g));
}
__device__ __forceinline__ void cp_commit(){ asm volatile("cp.async.commit_group;" ::: "memory"); }
__device__ __forceinline__ void cp_wait0(){ asm volatile("cp.async.wait_group 0;" ::: "memory"); }
__device__ __forceinline__ void cp_wait1(){ asm volatile("cp.async.wait_group 1;" ::: "memory"); }

__device__ __forceinline__ void ldm_x4(uint32_t* r, uint32_t a){
    asm volatile("ldmatrix.sync.aligned.m8n8.x4.shared.b16 {%0,%1,%2,%3}, [%4];"
        : "=r"(r[0]),"=r"(r[1]),"=r"(r[2]),"=r"(r[3]) : "r"(a));
}
__device__ __forceinline__ void mma16816(float* d, const uint32_t* a, const uint32_t* b){
    asm volatile("mma.sync.aligned.m16n8k16.row.col.f32.bf16.bf16.f32 "
        "{%0,%1,%2,%3}, {%4,%5,%6,%7}, {%8,%9}, {%0,%1,%2,%3};"
        : "+f"(d[0]),"+f"(d[1]),"+f"(d[2]),"+f"(d[3])
        : "r"(a[0]),"r"(a[1]),"r"(a[2]),"r"(a[3]), "r"(b[0]),"r"(b[1]));
}

// ---------------- bf16 HMMA GEMM (R12 config, frozen) -----------------------
template<int MODE, int BN>
__global__ __launch_bounds__(256, 2)
void mma_gemm(const __nv_bfloat16* __restrict__ Ah, const __nv_bfloat16* __restrict__ Al,
              const __nv_bfloat16* __restrict__ Bh, const __nv_bfloat16* __restrict__ Bl,
              int N, int K, float* __restrict__ C,
              __nv_bfloat16* __restrict__ Ch, __nv_bfloat16* __restrict__ Cl,
              const float* __restrict__ taps, const float* __restrict__ bias)
{
    constexpr int MT  = (BN == 128) ? 4 : 2;
    constexpr int NPR = MT / 2;                // mt pairs
    constexpr int STG = 16384 + BN*128;        // Ah+Al (16K) + Bh+Bl
    extern __shared__ char sm[];
    const int tid = threadIdx.x, lane = tid & 31, wid = tid >> 5;
    const int wm = (BN == 128) ? ((wid & 1) * 64) : ((wid & 3) * 32);
    const int wn = (BN == 128) ? ((wid >> 1) * 32) : ((wid >> 2) * 32);
    const int bm = blockIdx.y * 128, bn = blockIdx.x * BN;
    const int NC = K >> 5;
    const uint32_t smb = smem_u32(sm);

    float acc[MT][4][4];
#pragma unroll
    for (int a=0;a<MT;a++)
#pragma unroll
    for (int b=0;b<4;b++)
#pragma unroll
    for (int c=0;c<4;c++) acc[a][b][c] = 0.f;

    const __nv_bfloat16* srcs[4] = { Ah + (size_t)bm*K, Al + (size_t)bm*K,
                                     Bh + (size_t)bn*K, Bl + (size_t)bn*K };
    const int ldr = tid >> 2;          // 0..63
    const int ldc = tid & 3;           // 16B chunk within 64B row

    auto prefetch = [&](int ch){
        uint32_t sb = smb + (uint32_t)(ch % 3) * STG;
        int k0 = ch * 32;
#pragma unroll
        for (int i = 0; i < 4; i++){                       // A: Ah/Al, 128 rows
            int r = ldr + (i & 1) * 64;
            int mat = i >> 1;
            cpa16(sb + mat*8192u + (uint32_t)r*64u + ((uint32_t)(ldc ^ ((r >> 1) & 3)) << 4),
                  srcs[mat] + (size_t)r*K + k0 + ldc*8);
        }
        if (BN == 128){
#pragma unroll
            for (int i = 0; i < 4; i++){
                int r = ldr + (i & 1) * 64;
                int m = i >> 1;
                cpa16(sb + 16384u + m*8192u + (uint32_t)r*64u + ((uint32_t)(ldc ^ ((r >> 1) & 3)) << 4),
                      srcs[2 + m] + (size_t)r*K + k0 + ldc*8);
            }
        } else {
#pragma unroll
            for (int i = 0; i < 2; i++){
                int r = ldr;
                cpa16(sb + 16384u + i*(uint32_t)(BN*64) + (uint32_t)r*64u + ((uint32_t)(ldc ^ ((r >> 1) & 3)) << 4),
                      srcs[2 + i] + (size_t)r*K + k0 + ldc*8);
            }
        }
        cp_commit();
    };

    // ldmatrix lane geometry
    const int rA = (lane & 7) + ((lane >> 3) & 1) * 8;   // A row within 16
    const int cA = lane >> 4;                            // A k8-half 0/1
    const int jB = lane >> 3;                            // x4 matrix index
    const int ntOff = jB >> 1;                           // nt within pair
    const int cBn = jB & 1;                              // k8-half
    const int rBn = lane & 7;

    prefetch(0);
    prefetch(1);

    for (int ch = 0; ch < NC; ch++){
        if (ch + 1 < NC) cp_wait1(); else cp_wait0();
        __syncthreads();
        uint32_t sb  = smb + (uint32_t)(ch % 3) * STG;
        uint32_t sbB = sb + 16384u;

        uint32_t bh[4][2], bl[4][2];
        uint32_t ah[2][4], al[2][4];   // A frags for an mt PAIR

        auto loadB = [&](int kb){
#pragma unroll
            for (int p = 0; p < 2; p++){
                int nt = p*2 + ntOff;
                int row = wn + nt*8 + rBn;
                uint32_t off = (uint32_t)row*64u + ((uint32_t)((kb*2 + cBn) ^ ((row >> 1) & 3)) << 4);
                uint32_t t[4];
                ldm_x4(t, sbB + off);
                bh[p*2][0]=t[0]; bh[p*2][1]=t[1]; bh[p*2+1][0]=t[2]; bh[p*2+1][1]=t[3];
                ldm_x4(t, sbB + (uint32_t)(BN*64) + off);
                bl[p*2][0]=t[0]; bl[p*2][1]=t[1]; bl[p*2+1][0]=t[2]; bl[p*2+1][1]=t[3];
            }
        };
        auto loadApair = [&](int kb, int pr){
#pragma unroll
            for (int hh2 = 0; hh2 < 2; hh2++){
                int row = wm + (pr*2 + hh2)*16 + rA;
                uint32_t off = (uint32_t)row*64u + ((uint32_t)((kb*2 + cA) ^ ((row >> 1) & 3)) << 4);
                ldm_x4(ah[hh2], sb + off);
                ldm_x4(al[hh2], sb + 8192u + off);
            }
        };

        loadB(0);
        if (ch + 2 < NC) prefetch(ch + 2);

#pragma unroll
        for (int kb = 0; kb < 2; kb++){
#pragma unroll
            for (int pr = 0; pr < NPR; pr++){
                loadApair(kb, pr);
#pragma unroll
                for (int h2 = 0; h2 < 2; h2++)
#pragma unroll
                for (int nt = 0; nt < 4; nt++) mma16816(acc[pr*2+h2][nt], ah[h2], bh[nt]);
#pragma unroll
                for (int h2 = 0; h2 < 2; h2++)
#pragma unroll
                for (int nt = 0; nt < 4; nt++) mma16816(acc[pr*2+h2][nt], al[h2], bh[nt]);
#pragma unroll
                for (int h2 = 0; h2 < 2; h2++)
#pragma unroll
                for (int nt = 0; nt < 4; nt++) mma16816(acc[pr*2+h2][nt], ah[h2], bl[nt]);
                if (kb == 0 && pr == NPR - 1) loadB(1);
            }
        }
    }
    __syncthreads();

    // ------------------ epilogue ------------------
    if (MODE == 3){
        float* staps = (float*)sm;                 // [131][33]
        float* sbias = (float*)(sm + 17424);       // 128 floats
        const int d0g = bn >> 2;                   // 32 d-values per block
        for (int idx = tid; idx < 131*32; idx += 256){
            int i = idx >> 5, dd = idx & 31;
            int t = bm - 3 + i;
            staps[i*33 + dd] = (t >= 0) ? taps[(size_t)t*CONV_DIM + d0g + dd] : 0.f;
        }
        if (tid < 128) sbias[tid] = bias[bn + tid];
        __syncthreads();
#pragma unroll
        for (int mt = 0; mt < MT; mt++)
#pragma unroll
        for (int nt = 0; nt < 4; nt++){
            int cb = wn + nt*8 + (lane & 3)*2;     // kernel-col
            int dd = (cb >> 2) & 31;               // local d
            int w0 = cb & 3;                       // 0 or 2
            float b0 = sbias[cb], b1 = sbias[cb + 1];
#pragma unroll
            for (int rr = 0; rr < 2; rr++){
                int r = wm + mt*16 + (lane >> 2) + rr*8;
                float k0 = acc[mt][nt][rr*2 + 0] + b0;
                float k1 = acc[mt][nt][rr*2 + 1] + b1;
                float part = staps[(r + w0)*33 + dd]*k0 + staps[(r + w0 + 1)*33 + dd]*k1;
                float oth = __shfl_xor_sync(0xffffffffu, part, 1);
                if ((lane & 1) == 0)
                    C[(size_t)(bm + r)*CONV_DIM + d0g + dd] = siluf(part + oth);
            }
        }
    } else {
#pragma unroll
        for (int mt = 0; mt < MT; mt++)
#pragma unroll
        for (int nt = 0; nt < 4; nt++){
            int cb = wn + nt*8 + (lane & 3)*2;
#pragma unroll
            for (int rr = 0; rr < 2; rr++){
                int r = bm + wm + mt*16 + (lane >> 2) + rr*8;
                float v0 = acc[mt][nt][rr*2 + 0], v1 = acc[mt][nt][rr*2 + 1];
                size_t idx = (size_t)r*N + bn + cb;
                if (MODE == 2){ v0 = siluf(v0); v1 = siluf(v1); }
                if (MODE != 2) *(float2*)(C + idx) = make_float2(v0, v1);
                if (MODE >= 1){
                    __nv_bfloat16 h0 = __float2bfloat16(v0), h1 = __float2bfloat16(v1);
                    *(__nv_bfloat162*)(Ch + idx) = __halves2bfloat162(h0, h1);
                    __nv_bfloat16 l0 = __float2bfloat16(v0 - __bfloat162float(h0));
                    __nv_bfloat16 l1 = __float2bfloat16(v1 - __bfloat162float(h1));
                    *(__nv_bfloat162*)(Cl + idx) = __halves2bfloat162(l0, l1);
                }
            }
        }
    }
}

// ---------------- fp32 -> bf16 hi/lo split (row-major) ----------------------
__global__ __launch_bounds__(256)
void split4_kernel(const float* __restrict__ in, __nv_bfloat16* __restrict__ h,
                   __nv_bfloat16* __restrict__ l)
{
    int i = (blockIdx.x*256 + threadIdx.x)*4;
    float4 v = *(const float4*)(in + i);
    __nv_bfloat16 h0=__float2bfloat16(v.x), h1=__float2bfloat16(v.y),
                  h2=__float2bfloat16(v.z), h3=__float2bfloat16(v.w);
    h[i]=h0; h[i+1]=h1; h[i+2]=h2; h[i+3]=h3;
    l[i]  =__float2bfloat16(v.x-__bfloat162float(h0));
    l[i+1]=__float2bfloat16(v.y-__bfloat162float(h1));
    l[i+2]=__float2bfloat16(v.z-__bfloat162float(h2));
    l[i+3]=__float2bfloat16(v.w-__bfloat162float(h3));
}

// ---------------- fp32 [R,C] -> transposed bf16 hi/lo [C,R] v2 --------------
__global__ __launch_bounds__(256)
void transpose_split_kernel(const float* __restrict__ in, __nv_bfloat16* __restrict__ oh,
                            __nv_bfloat16* __restrict__ ol, int R, int C)
{
    __shared__ float t[64][65];
    const int tid = threadIdx.x;
    const int rb = blockIdx.y*64, cb = blockIdx.x*64;
    const int c4 = tid & 15;           // float4 col
    const int r0 = tid >> 4;           // 0..15
#pragma unroll
    for (int i = 0; i < 4; i++){
        int r = r0 + i*16;
        float4 v = *(const float4*)(in + (size_t)(rb+r)*C + cb + c4*4);
        t[r][c4*4+0]=v.x; t[r][c4*4+1]=v.y; t[r][c4*4+2]=v.z; t[r][c4*4+3]=v.w;
    }
    __syncthreads();
    const int rl = (tid & 31)*2;       // r pair
    const int cl0 = tid >> 5;          // 0..7
#pragma unroll
    for (int i = 0; i < 8; i++){
        int c = cl0 + i*8;
        float v0 = t[rl][c], v1 = t[rl+1][c];
        size_t idx = (size_t)(cb+c)*R + rb + rl;
        __nv_bfloat16 h0 = __float2bfloat16(v0), h1 = __float2bfloat16(v1);
        *(__nv_bfloat162*)(oh + idx) = __halves2bfloat162(h0, h1);
        __nv_bfloat16 l0 = __float2bfloat16(v0 - __bfloat162float(h0));
        __nv_bfloat16 l1 = __float2bfloat16(v1 - __bfloat162float(h1));
        *(__nv_bfloat162*)(ol + idx) = __halves2bfloat162(l0, l1);
    }
}

// ---------------- ba v2: smem-tiled GEMV, 32 rows/block ---------------------
__global__ __launch_bounds__(256)
void ba2_kernel(const float* __restrict__ x, const float* __restrict__ W_ba,
                float* __restrict__ beta, float* __restrict__ decay)
{
    __shared__ float sw[64][32];
    __shared__ float sx[32][64];
    const int tid = threadIdx.x, lane = tid & 31, w = tid >> 5;
    const int r0 = blockIdx.x * 32;

    float acc[4] = {0.f, 0.f, 0.f, 0.f};
    for (int k0 = 0; k0 < D_MODEL; k0 += 64){
        __syncthreads();
#pragma unroll
        for (int jj = 0; jj < 2; jj++){
            int i4 = tid + jj*256;
            { int row = i4 >> 3, cc = i4 & 7;
              *(float4*)&sw[row][cc*4] = *(const float4*)(W_ba + (size_t)(k0+row)*32 + cc*4); }
            { int row = i4 >> 4, cc = i4 & 15;
              *(float4*)&sx[row][cc*4] = *(const float4*)(x + (size_t)(r0+row)*D_MODEL + k0 + cc*4); }
        }
        __syncthreads();
#pragma unroll 16
        for (int kk = 0; kk < 64; kk++){
            float wv = sw[kk][lane];
#pragma unroll
            for (int rr = 0; rr < 4; rr++)
                acc[rr] = fmaf(sx[w*4 + rr][kk], wv, acc[rr]);
        }
    }
#pragma unroll
    for (int rr = 0; rr < 4; rr++){
        int t = r0 + w*4 + rr;
        if (lane < 16) beta[t*NH + lane]         = 1.0f / (1.0f + expf(-acc[rr]));
        else           decay[t*NH + (lane - 16)] = 1.0f / (1.0f + expf( acc[rr]));
    }
}

// ---------------- per-(t,h) l2norm scales + raw q.k dot ---------------------
__global__ __launch_bounds__(256)
void scale_kernel(const float* __restrict__ u, float* __restrict__ qs,
                  float* __restrict__ ks, float* __restrict__ qk)
{
    int gt = blockIdx.x * blockDim.x + threadIdx.x;
    int w = gt >> 5, lane = gt & 31;
    int t = w >> 4, h = w & 15;
    const float* base = u + (size_t)t*CONV_DIM + h*128;
    float4 a = *(const float4*)(base + lane*4);
    float sq = a.x*a.x + a.y*a.y + a.z*a.z + a.w*a.w;
    float4 b = *(const float4*)(base + 2048 + lane*4);
    float sk = b.x*b.x + b.y*b.y + b.z*b.z + b.w*b.w;
    float sqk = a.x*b.x + a.y*b.y + a.z*b.z + a.w*b.w;
#pragma unroll
    for (int m = 16; m >= 1; m >>= 1) {
        sq  += __shfl_xor_sync(0xffffffffu, sq, m);
        sk  += __shfl_xor_sync(0xffffffffu, sk, m);
        sqk += __shfl_xor_sync(0xffffffffu, sqk, m);
    }
    if (lane == 0) {
        qs[t*NH + h] = rsqrtf(sq + 1e-6f) * 0.08838834764831845f;
        ks[t*NH + h] = rsqrtf(sk + 1e-6f);
        qk[t*NH + h] = sqk;
    }
}

// ---------------- gated delta-rule scan v3 ----------------------------------
// o = q.S_new = eg*(q.S_old) + (q.k)*uk  with q.k precomputed -> the two
// 16-lane butterfly reductions (d1=k.S, d2=q.S) are now INDEPENDENT and
// interleave, halving the serial shfl latency per step.
#define CH 8
#define NCH (T_SEQ/CH)

__global__ __launch_bounds__(128)
void scan_kernel(const float* __restrict__ u,
                 const float* __restrict__ ksc_g, const float* __restrict__ qsc_g,
                 const float* __restrict__ beta_g, const float* __restrict__ decay_g,
                 const float* __restrict__ qk_g,
                 __nv_bfloat16* __restrict__ oh, __nv_bfloat16* __restrict__ ol)
{
    __shared__ float sk[2][CH][128];
    __shared__ float sq[2][CH][128];
    __shared__ float sv[2][CH][8];
    __shared__ float ss[2][CH][8];   // 5 scalars used, padded to 8

    const int tid = threadIdx.x, lane = tid & 31, warp = tid >> 5;
    const int h = blockIdx.y, vg = blockIdx.x;
    const int cw = lane >> 4;
    const int kg = lane & 15;
    const int col_local = warp*2 + cw;
    const int v = vg*8 + col_local;

    float s[8];
#pragma unroll
    for (int i=0;i<8;i++) s[i] = 0.f;

    auto prefetch = [&](int c, int b){
        int t0 = c*CH;
#pragma unroll
        for (int j2=0;j2<2;j2++){
            int idx = tid + j2*128;
            int st = idx >> 5, f4 = idx & 31;
            const float* rowbase = u + (size_t)(t0+st)*CONV_DIM + h*128 + f4*4;
            cpa16(smem_u32(&sq[b][st][f4*4]), rowbase);
            cpa16(smem_u32(&sk[b][st][f4*4]), rowbase + 2048);
        }
        if (tid < 16){
            int st = tid >> 1, f4 = tid & 1;
            cpa16(smem_u32(&sv[b][st][f4*4]),
                  u + (size_t)(t0+st)*CONV_DIM + 4096 + h*128 + vg*8 + f4*4);
        } else if (tid < 56){
            int r = tid - 16;
            int st = r & 7, wh = r >> 3;   // wh 0..4
            const float* src = (wh==0) ? ksc_g : (wh==1) ? qsc_g : (wh==2) ? beta_g
                              : (wh==3) ? decay_g : qk_g;
            cpa4(&ss[b][st][wh], src + (t0+st)*NH + h);
        }
    };

    prefetch(0, 0);
    cp_commit();

    for (int c = 0; c < NCH; c++){
        int b = c & 1;
        if (c+1 < NCH){
            prefetch(c+1, b^1);
            cp_commit();
            cp_wait1();
        } else {
            cp_wait0();
        }
        __syncthreads();

#pragma unroll
        for (int j = 0; j < CH; j++){
            float ksc = ss[b][j][0], qsc = ss[b][j][1];
            float bet = ss[b][j][2], eg  = ss[b][j][3];
            float qkt = ss[b][j][4];
            float vv  = sv[b][j][col_local];

            float kf[8], qf[8];
            *(float4*)&kf[0] = *(const float4*)&sk[b][j][kg*4];
            *(float4*)&kf[4] = *(const float4*)&sk[b][j][64 + kg*4];
            *(float4*)&qf[0] = *(const float4*)&sq[b][j][kg*4];
            *(float4*)&qf[4] = *(const float4*)&sq[b][j][64 + kg*4];

            // d1 = k.S_old, d2 = q.S_old — independent, interleaved chains
            float d1a=0.f, d1b=0.f, d2a=0.f, d2b=0.f;
#pragma unroll
            for (int i=0;i<8;i+=2){
                d1a = fmaf(kf[i],   s[i],   d1a);
                d1b = fmaf(kf[i+1], s[i+1], d1b);
                d2a = fmaf(qf[i],   s[i],   d2a);
                d2b = fmaf(qf[i+1], s[i+1], d2b);
            }
            float d1 = d1a + d1b;
            float d2 = d2a + d2b;
#pragma unroll
            for (int m = 1; m <= 8; m <<= 1){
                d1 += __shfl_xor_sync(0xffffffffu, d1, m);
                d2 += __shfl_xor_sync(0xffffffffu, d2, m);
            }
            float pred = d1 * ksc * eg;
            float uk = bet * (vv - pred) * ksc;
#pragma unroll
            for (int i=0;i<8;i++) s[i] = fmaf(eg, s[i], kf[i]*uk);
            // o = eg*d2 + (q.k)*uk
            float od = fmaf(qkt, uk, eg * d2);
            if (kg == 0){
                int t = c*CH + j;
                float ov = od * qsc;
                size_t idx = (size_t)t*(NH*128) + h*128 + v;
                __nv_bfloat16 h0 = __float2bfloat16(ov);
                oh[idx] = h0;
                ol[idx] = __float2bfloat16(ov - __bfloat162float(h0));
            }
        }
        __syncthreads();
    }
}

// ---------------- launch ----------------------------------------------------
#define DSMEM_128 (3*(16384 + 128*128))   // 98304
#define DSMEM_64  (3*(16384 + 64*128))    // 73728

extern "C" void kernel_launch(void* const* d_in, const int* in_sizes, int n_in,
                              void* d_out, int out_size)
{
    const float* x      = (const float*)d_in[0];
    const float* W_qkv  = (const float*)d_in[1];
    const float* W_ba   = (const float*)d_in[2];
    const float* gen_w1 = (const float*)d_in[3];
    const float* gen_w2 = (const float*)d_in[4];
    const float* gen_b2 = (const float*)d_in[5];
    const float* W_o    = (const float*)d_in[6];
    float* y = (float*)d_out;

    float *qkv, *u, *beta, *decay, *qs, *ks, *qk;
    cudaGetSymbolAddress((void**)&qkv,   g_qkv);
    cudaGetSymbolAddress((void**)&u,     g_u);
    cudaGetSymbolAddress((void**)&beta,  g_beta);
    cudaGetSymbolAddress((void**)&decay, g_decay);
    cudaGetSymbolAddress((void**)&qs,    g_qs);
    cudaGetSymbolAddress((void**)&ks,    g_ks);
    cudaGetSymbolAddress((void**)&qk,    g_qk);
    __nv_bfloat16 *xh,*xl,*qkvh,*qkvl,*hh,*hl,*oh,*ol;
    __nv_bfloat16 *wqkvh,*wqkvl,*w1h,*w1l,*w2h,*w2l,*woh,*wol;
    cudaGetSymbolAddress((void**)&xh, g_xh);     cudaGetSymbolAddress((void**)&xl, g_xl);
    cudaGetSymbolAddress((void**)&qkvh, g_qkvh); cudaGetSymbolAddress((void**)&qkvl, g_qkvl);
    cudaGetSymbolAddress((void**)&hh, g_hh);     cudaGetSymbolAddress((void**)&hl, g_hl);
    cudaGetSymbolAddress((void**)&oh, g_oh);     cudaGetSymbolAddress((void**)&ol, g_ol);
    cudaGetSymbolAddress((void**)&wqkvh, g_wqkvh); cudaGetSymbolAddress((void**)&wqkvl, g_wqkvl);
    cudaGetSymbolAddress((void**)&w1h, g_w1h);   cudaGetSymbolAddress((void**)&w1l, g_w1l);
    cudaGetSymbolAddress((void**)&w2h, g_w2h);   cudaGetSymbolAddress((void**)&w2l, g_w2l);
    cudaGetSymbolAddress((void**)&woh, g_woh);   cudaGetSymbolAddress((void**)&wol, g_wol);

    cudaFuncSetAttribute((const void*)mma_gemm<0,128>, cudaFuncAttributeMaxDynamicSharedMemorySize, DSMEM_128);
    cudaFuncSetAttribute((const void*)mma_gemm<1,128>, cudaFuncAttributeMaxDynamicSharedMemorySize, DSMEM_128);
    cudaFuncSetAttribute((const void*)mma_gemm<2,64>,  cudaFuncAttributeMaxDynamicSharedMemorySize, DSMEM_64);
    cudaFuncSetAttribute((const void*)mma_gemm<3,128>, cudaFuncAttributeMaxDynamicSharedMemorySize, DSMEM_128);

    // Launch order: ncu captures launch #4 -> keep qkv GEMM there.
    // 1) W_qkv transpose+split
    transpose_split_kernel<<<dim3(CONV_DIM/64, D_MODEL/64), 256>>>(W_qkv, wqkvh, wqkvl, D_MODEL, CONV_DIM);
    // 2) x split
    split4_kernel<<<(T_SEQ*D_MODEL)/1024, 256>>>(x, xh, xl);
    // 3) beta/decay
    ba2_kernel<<<T_SEQ/32, 256>>>(x, W_ba, beta, decay);
    // 4) qkv = x @ W_qkv   <-- ncu capture target
    mma_gemm<1,128><<<dim3(CONV_DIM/128, T_SEQ/128), 256, DSMEM_128>>>(
        xh, xl, wqkvh, wqkvl, CONV_DIM, D_MODEL, qkv, qkvh, qkvl, nullptr, nullptr);
    // 5) gen_w1 transpose+split
    transpose_split_kernel<<<dim3(GEN_HIDDEN/64, CONV_DIM/64), 256>>>(gen_w1, w1h, w1l, CONV_DIM, GEN_HIDDEN);
    // 6) gen_w2 transpose+split
    transpose_split_kernel<<<dim3(KERN_N/64, GEN_HIDDEN/64), 256>>>(gen_w2, w2h, w2l, GEN_HIDDEN, KERN_N);
    // 7) h = silu(qkv @ gen_w1)
    mma_gemm<2,64><<<dim3(GEN_HIDDEN/64, T_SEQ/128), 256, DSMEM_64>>>(
        qkvh, qkvl, w1h, w1l, GEN_HIDDEN, CONV_DIM, nullptr, hh, hl, nullptr, nullptr);
    // 8) u = silu(conv(qkv, h @ gen_w2 + b2))
    mma_gemm<3,128><<<dim3(KERN_N/128, T_SEQ/128), 256, DSMEM_128>>>(
        hh, hl, w2h, w2l, KERN_N, GEN_HIDDEN, u, nullptr, nullptr, qkv, gen_b2);
    // 9) scales + raw q.k
    scale_kernel<<<(T_SEQ*NH*32)/256, 256>>>(u, qs, ks, qk);
    // 10) scan -> oh/ol bf16 directly
    scan_kernel<<<dim3(16, NH), 128>>>(u, ks, qs, beta, decay, qk, oh, ol);
    // 11) W_o transpose+split
    transpose_split_kernel<<<dim3(D_MODEL/64, D_MODEL/64), 256>>>(W_o, woh, wol, D_MODEL, D_MODEL);
    // 12) y = o @ W_o
    mma_gemm<0,128><<<dim3(D_MODEL/128, T_SEQ/128), 256, DSMEM_128>>>(
        oh, ol, woh, wol, D_MODEL, D_MODEL, y, nullptr, nullptr, nullptr, nullptr);
}

// round 14
// speedup vs baseline: 1.0065x; 1.0065x over previous
#include <cuda_runtime.h>
#include <cuda_bf16.h>
#include <cstdint>

// Problem dims (fixed)
#define T_SEQ     2048
#define D_MODEL   2048
#define NH        16
#define CONV_DIM  6144
#define GEN_HIDDEN 768
#define KERN_N    (CONV_DIM*4)   // 24576

// ---------------- scratch (static __device__, no allocation) ----------------
__device__ float g_qkv [(size_t)T_SEQ*CONV_DIM];
__device__ float g_u   [(size_t)T_SEQ*CONV_DIM];
__device__ float g_hpart[(size_t)4*T_SEQ*GEN_HIDDEN];   // split-K partials (25MB)
__device__ float g_beta [T_SEQ*NH];
__device__ float g_decay[T_SEQ*NH];
__device__ float g_qs   [T_SEQ*NH];
__device__ float g_ks   [T_SEQ*NH];

// bf16 hi/lo split activations
__device__ __nv_bfloat16 g_xh  [(size_t)T_SEQ*D_MODEL],   g_xl  [(size_t)T_SEQ*D_MODEL];
__device__ __nv_bfloat16 g_qkvh[(size_t)T_SEQ*CONV_DIM],  g_qkvl[(size_t)T_SEQ*CONV_DIM];
__device__ __nv_bfloat16 g_hh  [(size_t)T_SEQ*GEN_HIDDEN],g_hl  [(size_t)T_SEQ*GEN_HIDDEN];
__device__ __nv_bfloat16 g_oh  [(size_t)T_SEQ*D_MODEL],   g_ol  [(size_t)T_SEQ*D_MODEL];
// bf16 hi/lo split transposed weights ([N,K] K-major)
__device__ __nv_bfloat16 g_wqkvh[(size_t)CONV_DIM*D_MODEL], g_wqkvl[(size_t)CONV_DIM*D_MODEL];
__device__ __nv_bfloat16 g_w1h [(size_t)GEN_HIDDEN*CONV_DIM], g_w1l [(size_t)GEN_HIDDEN*CONV_DIM];
__device__ __nv_bfloat16 g_w2h [(size_t)KERN_N*GEN_HIDDEN],  g_w2l [(size_t)KERN_N*GEN_HIDDEN];
__device__ __nv_bfloat16 g_woh [(size_t)D_MODEL*D_MODEL],    g_wol [(size_t)D_MODEL*D_MODEL];

__device__ __forceinline__ float siluf(float x){ return x / (1.0f + expf(-x)); }

// ---------------- PTX helpers (baseline ISA only: sm_80-level) --------------
__device__ __forceinline__ uint32_t smem_u32(const void* p){
    return (uint32_t)__cvta_generic_to_shared(p);
}
__device__ __forceinline__ void cpa16(uint32_t d, const void* g){
    asm volatile("cp.async.cg.shared.global [%0], [%1], 16;" :: "r"(d), "l"(g));
}
__device__ __forceinline__ void cpa4(const void* s, const void* g){
    asm volatile("cp.async.ca.shared.global [%0], [%1], 4;" :: "r"(smem_u32(s)), "l"(g));
}
__device__ __forceinline__ void cp_commit(){ asm volatile("cp.async.commit_group;" ::: "memory"); }
__device__ __forceinline__ void cp_wait0(){ asm volatile("cp.async.wait_group 0;" ::: "memory"); }
__device__ __forceinline__ void cp_wait1(){ asm volatile("cp.async.wait_group 1;" ::: "memory"); }

__device__ __forceinline__ void ldm_x4(uint32_t* r, uint32_t a){
    asm volatile("ldmatrix.sync.aligned.m8n8.x4.shared.b16 {%0,%1,%2,%3}, [%4];"
        : "=r"(r[0]),"=r"(r[1]),"=r"(r[2]),"=r"(r[3]) : "r"(a));
}
__device__ __forceinline__ void mma16816(float* d, const uint32_t* a, const uint32_t* b){
    asm volatile("mma.sync.aligned.m16n8k16.row.col.f32.bf16.bf16.f32 "
        "{%0,%1,%2,%3}, {%4,%5,%6,%7}, {%8,%9}, {%0,%1,%2,%3};"
        : "+f"(d[0]),"+f"(d[1]),"+f"(d[2]),"+f"(d[3])
        : "r"(a[0]),"r"(a[1]),"r"(a[2]),"r"(a[3]), "r"(b[0]),"r"(b[1]));
}

// ---------------- bf16 HMMA GEMM (R12 config, frozen mainloop) --------------
// 3-term split: Ah*Bh + Al*Bh + Ah*Bl, fp32 register accumulators.
// Tile 128xBN x Ksplit, 256 thr, 3-stage cp.async, swizzle c ^ ((row>>1)&3).
// Split-K: gridDim.z slices; slice z covers K in [z*Ksplit, (z+1)*Ksplit) and
// writes its own C partial at C + z*M*N. With gridDim.z==1, Ksplit==K this is
// bit-identical to the proven R12 kernel.
// MODE 0: C fp32
// MODE 1: C fp32 + Ch/Cl bf16 split        (qkv)
// MODE 3: dynamic-conv epilogue -> C fp32  (u); taps/bias extra inputs

template<int MODE, int BN>
__global__ __launch_bounds__(256, 2)
void mma_gemm(const __nv_bfloat16* __restrict__ Ah, const __nv_bfloat16* __restrict__ Al,
              const __nv_bfloat16* __restrict__ Bh, const __nv_bfloat16* __restrict__ Bl,
              int N, int K, int Ksplit, float* __restrict__ C,
              __nv_bfloat16* __restrict__ Ch, __nv_bfloat16* __restrict__ Cl,
              const float* __restrict__ taps, const float* __restrict__ bias)
{
    constexpr int MT  = (BN == 128) ? 4 : 2;
    constexpr int NPR = MT / 2;                // mt pairs
    constexpr int STG = 16384 + BN*128;        // Ah+Al (16K) + Bh+Bl
    extern __shared__ char sm[];
    const int tid = threadIdx.x, lane = tid & 31, wid = tid >> 5;
    const int wm = (BN == 128) ? ((wid & 1) * 64) : ((wid & 3) * 32);
    const int wn = (BN == 128) ? ((wid >> 1) * 32) : ((wid >> 2) * 32);
    const int bm = blockIdx.y * 128, bn = blockIdx.x * BN;
    const int NC = Ksplit >> 5;
    const int kbase = blockIdx.z * Ksplit;
    const uint32_t smb = smem_u32(sm);

    float acc[MT][4][4];
#pragma unroll
    for (int a=0;a<MT;a++)
#pragma unroll
    for (int b=0;b<4;b++)
#pragma unroll
    for (int c=0;c<4;c++) acc[a][b][c] = 0.f;

    const __nv_bfloat16* srcs[4] = { Ah + (size_t)bm*K, Al + (size_t)bm*K,
                                     Bh + (size_t)bn*K, Bl + (size_t)bn*K };
    const int ldr = tid >> 2;          // 0..63
    const int ldc = tid & 3;           // 16B chunk within 64B row

    auto prefetch = [&](int ch){
        uint32_t sb = smb + (uint32_t)(ch % 3) * STG;
        int k0 = kbase + ch * 32;
#pragma unroll
        for (int i = 0; i < 4; i++){                       // A: Ah/Al, 128 rows
            int r = ldr + (i & 1) * 64;
            int mat = i >> 1;
            cpa16(sb + mat*8192u + (uint32_t)r*64u + ((uint32_t)(ldc ^ ((r >> 1) & 3)) << 4),
                  srcs[mat] + (size_t)r*K + k0 + ldc*8);
        }
        if (BN == 128){
#pragma unroll
            for (int i = 0; i < 4; i++){
                int r = ldr + (i & 1) * 64;
                int m = i >> 1;
                cpa16(sb + 16384u + m*8192u + (uint32_t)r*64u + ((uint32_t)(ldc ^ ((r >> 1) & 3)) << 4),
                      srcs[2 + m] + (size_t)r*K + k0 + ldc*8);
            }
        } else {
#pragma unroll
            for (int i = 0; i < 2; i++){
                int r = ldr;
                cpa16(sb + 16384u + i*(uint32_t)(BN*64) + (uint32_t)r*64u + ((uint32_t)(ldc ^ ((r >> 1) & 3)) << 4),
                      srcs[2 + i] + (size_t)r*K + k0 + ldc*8);
            }
        }
        cp_commit();
    };

    // ldmatrix lane geometry
    const int rA = (lane & 7) + ((lane >> 3) & 1) * 8;   // A row within 16
    const int cA = lane >> 4;                            // A k8-half 0/1
    const int jB = lane >> 3;                            // x4 matrix index
    const int ntOff = jB >> 1;                           // nt within pair
    const int cBn = jB & 1;                              // k8-half
    const int rBn = lane & 7;

    prefetch(0);
    prefetch(1);

    for (int ch = 0; ch < NC; ch++){
        if (ch + 1 < NC) cp_wait1(); else cp_wait0();
        __syncthreads();
        uint32_t sb  = smb + (uint32_t)(ch % 3) * STG;
        uint32_t sbB = sb + 16384u;

        uint32_t bh[4][2], bl[4][2];
        uint32_t ah[2][4], al[2][4];   // A frags for an mt PAIR

        auto loadB = [&](int kb){
#pragma unroll
            for (int p = 0; p < 2; p++){
                int nt = p*2 + ntOff;
                int row = wn + nt*8 + rBn;
                uint32_t off = (uint32_t)row*64u + ((uint32_t)((kb*2 + cBn) ^ ((row >> 1) & 3)) << 4);
                uint32_t t[4];
                ldm_x4(t, sbB + off);
                bh[p*2][0]=t[0]; bh[p*2][1]=t[1]; bh[p*2+1][0]=t[2]; bh[p*2+1][1]=t[3];
                ldm_x4(t, sbB + (uint32_t)(BN*64) + off);
                bl[p*2][0]=t[0]; bl[p*2][1]=t[1]; bl[p*2+1][0]=t[2]; bl[p*2+1][1]=t[3];
            }
        };
        auto loadApair = [&](int kb, int pr){
#pragma unroll
            for (int hh2 = 0; hh2 < 2; hh2++){
                int row = wm + (pr*2 + hh2)*16 + rA;
                uint32_t off = (uint32_t)row*64u + ((uint32_t)((kb*2 + cA) ^ ((row >> 1) & 3)) << 4);
                ldm_x4(ah[hh2], sb + off);
                ldm_x4(al[hh2], sb + 8192u + off);
            }
        };

        loadB(0);
        if (ch + 2 < NC) prefetch(ch + 2);

#pragma unroll
        for (int kb = 0; kb < 2; kb++){
#pragma unroll
            for (int pr = 0; pr < NPR; pr++){
                loadApair(kb, pr);
#pragma unroll
                for (int h2 = 0; h2 < 2; h2++)
#pragma unroll
                for (int nt = 0; nt < 4; nt++) mma16816(acc[pr*2+h2][nt], ah[h2], bh[nt]);
#pragma unroll
                for (int h2 = 0; h2 < 2; h2++)
#pragma unroll
                for (int nt = 0; nt < 4; nt++) mma16816(acc[pr*2+h2][nt], al[h2], bh[nt]);
#pragma unroll
                for (int h2 = 0; h2 < 2; h2++)
#pragma unroll
                for (int nt = 0; nt < 4; nt++) mma16816(acc[pr*2+h2][nt], ah[h2], bl[nt]);
                if (kb == 0 && pr == NPR - 1) loadB(1);
            }
        }
    }
    __syncthreads();

    float* Cz = C + (size_t)blockIdx.z * ((size_t)gridDim.y * 128) * N;

    // ------------------ epilogue ------------------
    if (MODE == 3){
        float* staps = (float*)sm;                 // [131][33]
        float* sbias = (float*)(sm + 17424);       // 128 floats
        const int d0g = bn >> 2;                   // 32 d-values per block
        for (int idx = tid; idx < 131*32; idx += 256){
            int i = idx >> 5, dd = idx & 31;
            int t = bm - 3 + i;
            staps[i*33 + dd] = (t >= 0) ? taps[(size_t)t*CONV_DIM + d0g + dd] : 0.f;
        }
        if (tid < 128) sbias[tid] = bias[bn + tid];
        __syncthreads();
#pragma unroll
        for (int mt = 0; mt < MT; mt++)
#pragma unroll
        for (int nt = 0; nt < 4; nt++){
            int cb = wn + nt*8 + (lane & 3)*2;     // kernel-col
            int dd = (cb >> 2) & 31;               // local d
            int w0 = cb & 3;                       // 0 or 2
            float b0 = sbias[cb], b1 = sbias[cb + 1];
#pragma unroll
            for (int rr = 0; rr < 2; rr++){
                int r = wm + mt*16 + (lane >> 2) + rr*8;
                float k0 = acc[mt][nt][rr*2 + 0] + b0;
                float k1 = acc[mt][nt][rr*2 + 1] + b1;
                float part = staps[(r + w0)*33 + dd]*k0 + staps[(r + w0 + 1)*33 + dd]*k1;
                float oth = __shfl_xor_sync(0xffffffffu, part, 1);
                if ((lane & 1) == 0)
                    Cz[(size_t)(bm + r)*CONV_DIM + d0g + dd] = siluf(part + oth);
            }
        }
    } else {
#pragma unroll
        for (int mt = 0; mt < MT; mt++)
#pragma unroll
        for (int nt = 0; nt < 4; nt++){
            int cb = wn + nt*8 + (lane & 3)*2;
#pragma unroll
            for (int rr = 0; rr < 2; rr++){
                int r = bm + wm + mt*16 + (lane >> 2) + rr*8;
                float v0 = acc[mt][nt][rr*2 + 0], v1 = acc[mt][nt][rr*2 + 1];
                size_t idx = (size_t)r*N + bn + cb;
                *(float2*)(Cz + idx) = make_float2(v0, v1);
                if (MODE == 1){
                    __nv_bfloat16 h0 = __float2bfloat16(v0), h1 = __float2bfloat16(v1);
                    *(__nv_bfloat162*)(Ch + idx) = __halves2bfloat162(h0, h1);
                    __nv_bfloat16 l0 = __float2bfloat16(v0 - __bfloat162float(h0));
                    __nv_bfloat16 l1 = __float2bfloat16(v1 - __bfloat162float(h1));
                    *(__nv_bfloat162*)(Cl + idx) = __halves2bfloat162(l0, l1);
                }
            }
        }
    }
}

// ---------------- merge split-K partials -> silu -> bf16 hi/lo --------------
__global__ __launch_bounds__(256)
void merge_h_kernel(const float* __restrict__ part,
                    __nv_bfloat16* __restrict__ hh, __nv_bfloat16* __restrict__ hl)
{
    const size_t P = (size_t)T_SEQ * GEN_HIDDEN;
    size_t i = ((size_t)blockIdx.x * 256 + threadIdx.x) * 4;
    float4 a = *(const float4*)(part + i);
    float4 b = *(const float4*)(part + P + i);
    float4 c = *(const float4*)(part + 2*P + i);
    float4 d = *(const float4*)(part + 3*P + i);
    float v[4] = { siluf(a.x+b.x+c.x+d.x), siluf(a.y+b.y+c.y+d.y),
                   siluf(a.z+b.z+c.z+d.z), siluf(a.w+b.w+c.w+d.w) };
#pragma unroll
    for (int j = 0; j < 4; j++){
        __nv_bfloat16 h0 = __float2bfloat16(v[j]);
        hh[i+j] = h0;
        hl[i+j] = __float2bfloat16(v[j] - __bfloat162float(h0));
    }
}

// ---------------- fp32 -> bf16 hi/lo split (row-major) ----------------------
__global__ __launch_bounds__(256)
void split4_kernel(const float* __restrict__ in, __nv_bfloat16* __restrict__ h,
                   __nv_bfloat16* __restrict__ l)
{
    int i = (blockIdx.x*256 + threadIdx.x)*4;
    float4 v = *(const float4*)(in + i);
    __nv_bfloat16 h0=__float2bfloat16(v.x), h1=__float2bfloat16(v.y),
                  h2=__float2bfloat16(v.z), h3=__float2bfloat16(v.w);
    h[i]=h0; h[i+1]=h1; h[i+2]=h2; h[i+3]=h3;
    l[i]  =__float2bfloat16(v.x-__bfloat162float(h0));
    l[i+1]=__float2bfloat16(v.y-__bfloat162float(h1));
    l[i+2]=__float2bfloat16(v.z-__bfloat162float(h2));
    l[i+3]=__float2bfloat16(v.w-__bfloat162float(h3));
}

// ---------------- fp32 [R,C] -> transposed bf16 hi/lo [C,R] v2 --------------
__global__ __launch_bounds__(256)
void transpose_split_kernel(const float* __restrict__ in, __nv_bfloat16* __restrict__ oh,
                            __nv_bfloat16* __restrict__ ol, int R, int C)
{
    __shared__ float t[64][65];
    const int tid = threadIdx.x;
    const int rb = blockIdx.y*64, cb = blockIdx.x*64;
    const int c4 = tid & 15;           // float4 col
    const int r0 = tid >> 4;           // 0..15
#pragma unroll
    for (int i = 0; i < 4; i++){
        int r = r0 + i*16;
        float4 v = *(const float4*)(in + (size_t)(rb+r)*C + cb + c4*4);
        t[r][c4*4+0]=v.x; t[r][c4*4+1]=v.y; t[r][c4*4+2]=v.z; t[r][c4*4+3]=v.w;
    }
    __syncthreads();
    const int rl = (tid & 31)*2;       // r pair
    const int cl0 = tid >> 5;          // 0..7
#pragma unroll
    for (int i = 0; i < 8; i++){
        int c = cl0 + i*8;
        float v0 = t[rl][c], v1 = t[rl+1][c];
        size_t idx = (size_t)(cb+c)*R + rb + rl;
        __nv_bfloat16 h0 = __float2bfloat16(v0), h1 = __float2bfloat16(v1);
        *(__nv_bfloat162*)(oh + idx) = __halves2bfloat162(h0, h1);
        __nv_bfloat16 l0 = __float2bfloat16(v0 - __bfloat162float(h0));
        __nv_bfloat16 l1 = __float2bfloat16(v1 - __bfloat162float(h1));
        *(__nv_bfloat162*)(ol + idx) = __halves2bfloat162(l0, l1);
    }
}

// ---------------- ba v2: smem-tiled GEMV, 32 rows/block ---------------------
__global__ __launch_bounds__(256)
void ba2_kernel(const float* __restrict__ x, const float* __restrict__ W_ba,
                float* __restrict__ beta, float* __restrict__ decay)
{
    __shared__ float sw[64][32];
    __shared__ float sx[32][64];
    const int tid = threadIdx.x, lane = tid & 31, w = tid >> 5;
    const int r0 = blockIdx.x * 32;

    float acc[4] = {0.f, 0.f, 0.f, 0.f};
    for (int k0 = 0; k0 < D_MODEL; k0 += 64){
        __syncthreads();
#pragma unroll
        for (int jj = 0; jj < 2; jj++){
            int i4 = tid + jj*256;
            { int row = i4 >> 3, cc = i4 & 7;
              *(float4*)&sw[row][cc*4] = *(const float4*)(W_ba + (size_t)(k0+row)*32 + cc*4); }
            { int row = i4 >> 4, cc = i4 & 15;
              *(float4*)&sx[row][cc*4] = *(const float4*)(x + (size_t)(r0+row)*D_MODEL + k0 + cc*4); }
        }
        __syncthreads();
#pragma unroll 16
        for (int kk = 0; kk < 64; kk++){
            float wv = sw[kk][lane];
#pragma unroll
            for (int rr = 0; rr < 4; rr++)
                acc[rr] = fmaf(sx[w*4 + rr][kk], wv, acc[rr]);
        }
    }
#pragma unroll
    for (int rr = 0; rr < 4; rr++){
        int t = r0 + w*4 + rr;
        if (lane < 16) beta[t*NH + lane]         = 1.0f / (1.0f + expf(-acc[rr]));
        else           decay[t*NH + (lane - 16)] = 1.0f / (1.0f + expf( acc[rr]));
    }
}

// ---------------- per-(t,h) l2norm scales for q,k ---------------------------
__global__ __launch_bounds__(256)
void scale_kernel(const float* __restrict__ u, float* __restrict__ qs, float* __restrict__ ks)
{
    int gt = blockIdx.x * blockDim.x + threadIdx.x;
    int w = gt >> 5, lane = gt & 31;
    int t = w >> 4, h = w & 15;
    const float* base = u + (size_t)t*CONV_DIM + h*128;
    float4 a = *(const float4*)(base + lane*4);
    float sq = a.x*a.x + a.y*a.y + a.z*a.z + a.w*a.w;
    float4 b = *(const float4*)(base + 2048 + lane*4);
    float sk = b.x*b.x + b.y*b.y + b.z*b.z + b.w*b.w;
#pragma unroll
    for (int m = 16; m >= 1; m >>= 1) {
        sq += __shfl_xor_sync(0xffffffffu, sq, m);
        sk += __shfl_xor_sync(0xffffffffu, sk, m);
    }
    if (lane == 0) {
        qs[t*NH + h] = rsqrtf(sq + 1e-6f) * 0.08838834764831845f;
        ks[t*NH + h] = rsqrtf(sk + 1e-6f);
    }
}

// ---------------- gated delta-rule scan v2 (R12 proven) ---------------------
#define CH 8
#define NCH (T_SEQ/CH)

__global__ __launch_bounds__(128)
void scan_kernel(const float* __restrict__ u,
                 const float* __restrict__ ksc_g, const float* __restrict__ qsc_g,
                 const float* __restrict__ beta_g, const float* __restrict__ decay_g,
                 __nv_bfloat16* __restrict__ oh, __nv_bfloat16* __restrict__ ol)
{
    __shared__ float sk[2][CH][128];
    __shared__ float sq[2][CH][128];
    __shared__ float sv[2][CH][8];
    __shared__ float ss[2][CH][4];

    const int tid = threadIdx.x, lane = tid & 31, warp = tid >> 5;
    const int h = blockIdx.y, vg = blockIdx.x;
    const int cw = lane >> 4;
    const int kg = lane & 15;
    const int col_local = warp*2 + cw;
    const int v = vg*8 + col_local;

    float s[8];
#pragma unroll
    for (int i=0;i<8;i++) s[i] = 0.f;

    auto prefetch = [&](int c, int b){
        int t0 = c*CH;
#pragma unroll
        for (int j2=0;j2<2;j2++){
            int idx = tid + j2*128;
            int st = idx >> 5, f4 = idx & 31;
            const float* rowbase = u + (size_t)(t0+st)*CONV_DIM + h*128 + f4*4;
            cpa16(smem_u32(&sq[b][st][f4*4]), rowbase);
            cpa16(smem_u32(&sk[b][st][f4*4]), rowbase + 2048);
        }
        if (tid < 16){
            int st = tid >> 1, f4 = tid & 1;
            cpa16(smem_u32(&sv[b][st][f4*4]),
                  u + (size_t)(t0+st)*CONV_DIM + 4096 + h*128 + vg*8 + f4*4);
        } else if (tid < 48){
            int r = tid - 16;
            int st = r & 7, wh = r >> 3;
            const float* src = (wh==0) ? ksc_g : (wh==1) ? qsc_g : (wh==2) ? beta_g : decay_g;
            cpa4(&ss[b][st][wh], src + (t0+st)*NH + h);
        }
    };

    prefetch(0, 0);
    cp_commit();

    for (int c = 0; c < NCH; c++){
        int b = c & 1;
        if (c+1 < NCH){
            prefetch(c+1, b^1);
            cp_commit();
            cp_wait1();
        } else {
            cp_wait0();
        }
        __syncthreads();

#pragma unroll
        for (int j = 0; j < CH; j++){
            float ksc = ss[b][j][0], qsc = ss[b][j][1];
            float bet = ss[b][j][2], eg  = ss[b][j][3];
            float vv  = sv[b][j][col_local];

            float kf[8], qf[8];
            *(float4*)&kf[0] = *(const float4*)&sk[b][j][kg*4];
            *(float4*)&kf[4] = *(const float4*)&sk[b][j][64 + kg*4];
            *(float4*)&qf[0] = *(const float4*)&sq[b][j][kg*4];
            *(float4*)&qf[4] = *(const float4*)&sq[b][j][64 + kg*4];

            float a0=0.f, a1=0.f;
#pragma unroll
            for (int i=0;i<8;i+=2){ a0 = fmaf(kf[i], s[i], a0); a1 = fmaf(kf[i+1], s[i+1], a1); }
            float dot = a0 + a1;
            dot += __shfl_xor_sync(0xffffffffu, dot, 1);
            dot += __shfl_xor_sync(0xffffffffu, dot, 2);
            dot += __shfl_xor_sync(0xffffffffu, dot, 4);
            dot += __shfl_xor_sync(0xffffffffu, dot, 8);
            float pred = dot * ksc * eg;
            float uk = bet * (vv - pred) * ksc;
#pragma unroll
            for (int i=0;i<8;i++) s[i] = fmaf(eg, s[i], kf[i]*uk);
            float c0=0.f, c1=0.f;
#pragma unroll
            for (int i=0;i<8;i+=2){ c0 = fmaf(qf[i], s[i], c0); c1 = fmaf(qf[i+1], s[i+1], c1); }
            float od = c0 + c1;
            od += __shfl_xor_sync(0xffffffffu, od, 1);
            od += __shfl_xor_sync(0xffffffffu, od, 2);
            od += __shfl_xor_sync(0xffffffffu, od, 4);
            od += __shfl_xor_sync(0xffffffffu, od, 8);
            if (kg == 0){
                int t = c*CH + j;
                float ov = od * qsc;
                size_t idx = (size_t)t*(NH*128) + h*128 + v;
                __nv_bfloat16 h0 = __float2bfloat16(ov);
                oh[idx] = h0;
                ol[idx] = __float2bfloat16(ov - __bfloat162float(h0));
            }
        }
        __syncthreads();
    }
}

// ---------------- launch ----------------------------------------------------
#define DSMEM_128 (3*(16384 + 128*128))   // 98304
#define DSMEM_64  (3*(16384 + 64*128))    // 73728

extern "C" void kernel_launch(void* const* d_in, const int* in_sizes, int n_in,
                              void* d_out, int out_size)
{
    const float* x      = (const float*)d_in[0];
    const float* W_qkv  = (const float*)d_in[1];
    const float* W_ba   = (const float*)d_in[2];
    const float* gen_w1 = (const float*)d_in[3];
    const float* gen_w2 = (const float*)d_in[4];
    const float* gen_b2 = (const float*)d_in[5];
    const float* W_o    = (const float*)d_in[6];
    float* y = (float*)d_out;

    float *qkv, *u, *hpart, *beta, *decay, *qs, *ks;
    cudaGetSymbolAddress((void**)&qkv,   g_qkv);
    cudaGetSymbolAddress((void**)&u,     g_u);
    cudaGetSymbolAddress((void**)&hpart, g_hpart);
    cudaGetSymbolAddress((void**)&beta,  g_beta);
    cudaGetSymbolAddress((void**)&decay, g_decay);
    cudaGetSymbolAddress((void**)&qs,    g_qs);
    cudaGetSymbolAddress((void**)&ks,    g_ks);
    __nv_bfloat16 *xh,*xl,*qkvh,*qkvl,*hh,*hl,*oh,*ol;
    __nv_bfloat16 *wqkvh,*wqkvl,*w1h,*w1l,*w2h,*w2l,*woh,*wol;
    cudaGetSymbolAddress((void**)&xh, g_xh);     cudaGetSymbolAddress((void**)&xl, g_xl);
    cudaGetSymbolAddress((void**)&qkvh, g_qkvh); cudaGetSymbolAddress((void**)&qkvl, g_qkvl);
    cudaGetSymbolAddress((void**)&hh, g_hh);     cudaGetSymbolAddress((void**)&hl, g_hl);
    cudaGetSymbolAddress((void**)&oh, g_oh);     cudaGetSymbolAddress((void**)&ol, g_ol);
    cudaGetSymbolAddress((void**)&wqkvh, g_wqkvh); cudaGetSymbolAddress((void**)&wqkvl, g_wqkvl);
    cudaGetSymbolAddress((void**)&w1h, g_w1h);   cudaGetSymbolAddress((void**)&w1l, g_w1l);
    cudaGetSymbolAddress((void**)&w2h, g_w2h);   cudaGetSymbolAddress((void**)&w2l, g_w2l);
    cudaGetSymbolAddress((void**)&woh, g_woh);   cudaGetSymbolAddress((void**)&wol, g_wol);

    cudaFuncSetAttribute((const void*)mma_gemm<0,128>, cudaFuncAttributeMaxDynamicSharedMemorySize, DSMEM_128);
    cudaFuncSetAttribute((const void*)mma_gemm<1,128>, cudaFuncAttributeMaxDynamicSharedMemorySize, DSMEM_128);
    cudaFuncSetAttribute((const void*)mma_gemm<0,64>,  cudaFuncAttributeMaxDynamicSharedMemorySize, DSMEM_64);
    cudaFuncSetAttribute((const void*)mma_gemm<3,128>, cudaFuncAttributeMaxDynamicSharedMemorySize, DSMEM_128);

    // Launch order: ncu captures launch #4 -> keep qkv GEMM there.
    // 1) W_qkv transpose+split
    transpose_split_kernel<<<dim3(CONV_DIM/64, D_MODEL/64), 256>>>(W_qkv, wqkvh, wqkvl, D_MODEL, CONV_DIM);
    // 2) x split
    split4_kernel<<<(T_SEQ*D_MODEL)/1024, 256>>>(x, xh, xl);
    // 3) beta/decay
    ba2_kernel<<<T_SEQ/32, 256>>>(x, W_ba, beta, decay);
    // 4) qkv = x @ W_qkv   <-- ncu capture target
    mma_gemm<1,128><<<dim3(CONV_DIM/128, T_SEQ/128), 256, DSMEM_128>>>(
        xh, xl, wqkvh, wqkvl, CONV_DIM, D_MODEL, D_MODEL, qkv, qkvh, qkvl, nullptr, nullptr);
    // 5) gen_w1 transpose+split
    transpose_split_kernel<<<dim3(GEN_HIDDEN/64, CONV_DIM/64), 256>>>(gen_w1, w1h, w1l, CONV_DIM, GEN_HIDDEN);
    // 6) gen_w2 transpose+split
    transpose_split_kernel<<<dim3(KERN_N/64, GEN_HIDDEN/64), 256>>>(gen_w2, w2h, w2l, GEN_HIDDEN, KERN_N);
    // 7) h partials: split-K=4 over K=6144 (768 blocks = 5.2 full waves)
    mma_gemm<0,64><<<dim3(GEN_HIDDEN/64, T_SEQ/128, 4), 256, DSMEM_64>>>(
        qkvh, qkvl, w1h, w1l, GEN_HIDDEN, CONV_DIM, CONV_DIM/4, hpart, nullptr, nullptr, nullptr, nullptr);
    // 8) merge partials -> silu -> hh/hl
    merge_h_kernel<<<(T_SEQ*GEN_HIDDEN)/1024, 256>>>(hpart, hh, hl);
    // 9) u = silu(conv(qkv, h @ gen_w2 + b2))
    mma_gemm<3,128><<<dim3(KERN_N/128, T_SEQ/128), 256, DSMEM_128>>>(
        hh, hl, w2h, w2l, KERN_N, GEN_HIDDEN, GEN_HIDDEN, u, nullptr, nullptr, qkv, gen_b2);
    // 10) scales
    scale_kernel<<<(T_SEQ*NH*32)/256, 256>>>(u, qs, ks);
    // 11) scan -> oh/ol bf16 directly
    scan_kernel<<<dim3(16, NH), 128>>>(u, ks, qs, beta, decay, oh, ol);
    // 12) W_o transpose+split
    transpose_split_kernel<<<dim3(D_MODEL/64, D_MODEL/64), 256>>>(W_o, woh, wol, D_MODEL, D_MODEL);
    // 13) y = o @ W_o  (BN=64: 512 blocks = 3.5 waves, smaller tail)
    mma_gemm<0,64><<<dim3(D_MODEL/64, T_SEQ/128), 256, DSMEM_64>>>(
        oh, ol, woh, wol, D_MODEL, D_MODEL, D_MODEL, y, nullptr, nullptr, nullptr, nullptr);
}

// round 15
// speedup vs baseline: 1.0344x; 1.0277x over previous
#include <cuda_runtime.h>
#include <cuda_bf16.h>
#include <cstdint>

// Problem dims (fixed)
#define T_SEQ     2048
#define D_MODEL   2048
#define NH        16
#define CONV_DIM  6144
#define GEN_HIDDEN 768
#define KERN_N    (CONV_DIM*4)   // 24576

// ---------------- scratch (static __device__, no allocation) ----------------
__device__ float g_u   [(size_t)T_SEQ*CONV_DIM];
__device__ float g_hpart[(size_t)4*T_SEQ*GEN_HIDDEN];   // split-K partials
__device__ float g_beta [T_SEQ*NH];
__device__ float g_decay[T_SEQ*NH];
__device__ float g_qs   [T_SEQ*NH];
__device__ float g_ks   [T_SEQ*NH];

// bf16 hi/lo split activations
__device__ __nv_bfloat16 g_xh  [(size_t)T_SEQ*D_MODEL],   g_xl  [(size_t)T_SEQ*D_MODEL];
__device__ __nv_bfloat16 g_qkvh[(size_t)T_SEQ*CONV_DIM],  g_qkvl[(size_t)T_SEQ*CONV_DIM];
__device__ __nv_bfloat16 g_hh  [(size_t)T_SEQ*GEN_HIDDEN],g_hl  [(size_t)T_SEQ*GEN_HIDDEN];
__device__ __nv_bfloat16 g_oh  [(size_t)T_SEQ*D_MODEL],   g_ol  [(size_t)T_SEQ*D_MODEL];
// bf16 hi/lo split transposed weights ([N,K] K-major)
__device__ __nv_bfloat16 g_wqkvh[(size_t)CONV_DIM*D_MODEL], g_wqkvl[(size_t)CONV_DIM*D_MODEL];
__device__ __nv_bfloat16 g_w1h [(size_t)GEN_HIDDEN*CONV_DIM], g_w1l [(size_t)GEN_HIDDEN*CONV_DIM];
__device__ __nv_bfloat16 g_w2h [(size_t)KERN_N*GEN_HIDDEN],  g_w2l [(size_t)KERN_N*GEN_HIDDEN];
__device__ __nv_bfloat16 g_woh [(size_t)D_MODEL*D_MODEL],    g_wol [(size_t)D_MODEL*D_MODEL];

__device__ __forceinline__ float siluf(float x){ return x / (1.0f + expf(-x)); }

// ---------------- PTX helpers (baseline ISA only: sm_80-level) --------------
__device__ __forceinline__ uint32_t smem_u32(const void* p){
    return (uint32_t)__cvta_generic_to_shared(p);
}
__device__ __forceinline__ void cpa16(uint32_t d, const void* g){
    asm volatile("cp.async.cg.shared.global [%0], [%1], 16;" :: "r"(d), "l"(g));
}
__device__ __forceinline__ void cpa4(const void* s, const void* g){
    asm volatile("cp.async.ca.shared.global [%0], [%1], 4;" :: "r"(smem_u32(s)), "l"(g));
}
__device__ __forceinline__ void cp_commit(){ asm volatile("cp.async.commit_group;" ::: "memory"); }
__device__ __forceinline__ void cp_wait0(){ asm volatile("cp.async.wait_group 0;" ::: "memory"); }
__device__ __forceinline__ void cp_wait1(){ asm volatile("cp.async.wait_group 1;" ::: "memory"); }

__device__ __forceinline__ void ldm_x4(uint32_t* r, uint32_t a){
    asm volatile("ldmatrix.sync.aligned.m8n8.x4.shared.b16 {%0,%1,%2,%3}, [%4];"
        : "=r"(r[0]),"=r"(r[1]),"=r"(r[2]),"=r"(r[3]) : "r"(a));
}
__device__ __forceinline__ void mma16816(float* d, const uint32_t* a, const uint32_t* b){
    asm volatile("mma.sync.aligned.m16n8k16.row.col.f32.bf16.bf16.f32 "
        "{%0,%1,%2,%3}, {%4,%5,%6,%7}, {%8,%9}, {%0,%1,%2,%3};"
        : "+f"(d[0]),"+f"(d[1]),"+f"(d[2]),"+f"(d[3])
        : "r"(a[0]),"r"(a[1]),"r"(a[2]),"r"(a[3]), "r"(b[0]),"r"(b[1]));
}

// ---------------- bf16 HMMA GEMM (frozen mainloop + prefetch reposition) ----
// 3-term split: Ah*Bh + Al*Bh + Ah*Bl, fp32 register accumulators.
// Tile 128xBN x Ksplit, 256 thr, 3-stage cp.async, swizzle c ^ ((row>>1)&3).
// Split-K via gridDim.z (z-slice partial written at C + z*M*N).
// MODE 0: C fp32
// MODE 1: Ch/Cl bf16 split only (no fp32 C)    (qkv)
// MODE 3: dynamic-conv epilogue -> C fp32 (u); taps from bf16 hi/lo pair

template<int MODE, int BN>
__global__ __launch_bounds__(256, 2)
void mma_gemm(const __nv_bfloat16* __restrict__ Ah, const __nv_bfloat16* __restrict__ Al,
              const __nv_bfloat16* __restrict__ Bh, const __nv_bfloat16* __restrict__ Bl,
              int N, int K, int Ksplit, float* __restrict__ C,
              __nv_bfloat16* __restrict__ Ch, __nv_bfloat16* __restrict__ Cl,
              const __nv_bfloat16* __restrict__ tapsh, const __nv_bfloat16* __restrict__ tapsl,
              const float* __restrict__ bias)
{
    constexpr int MT  = (BN == 128) ? 4 : 2;
    constexpr int NPR = MT / 2;                // mt pairs
    constexpr int STG = 16384 + BN*128;        // Ah+Al (16K) + Bh+Bl
    extern __shared__ char sm[];
    const int tid = threadIdx.x, lane = tid & 31, wid = tid >> 5;
    const int wm = (BN == 128) ? ((wid & 1) * 64) : ((wid & 3) * 32);
    const int wn = (BN == 128) ? ((wid >> 1) * 32) : ((wid >> 2) * 32);
    const int bm = blockIdx.y * 128, bn = blockIdx.x * BN;
    const int NC = Ksplit >> 5;
    const int kbase = blockIdx.z * Ksplit;
    const uint32_t smb = smem_u32(sm);

    float acc[MT][4][4];
#pragma unroll
    for (int a=0;a<MT;a++)
#pragma unroll
    for (int b=0;b<4;b++)
#pragma unroll
    for (int c=0;c<4;c++) acc[a][b][c] = 0.f;

    const __nv_bfloat16* srcs[4] = { Ah + (size_t)bm*K, Al + (size_t)bm*K,
                                     Bh + (size_t)bn*K, Bl + (size_t)bn*K };
    const int ldr = tid >> 2;          // 0..63
    const int ldc = tid & 3;           // 16B chunk within 64B row

    auto prefetch = [&](int ch){
        uint32_t sb = smb + (uint32_t)(ch % 3) * STG;
        int k0 = kbase + ch * 32;
#pragma unroll
        for (int i = 0; i < 4; i++){                       // A: Ah/Al, 128 rows
            int r = ldr + (i & 1) * 64;
            int mat = i >> 1;
            cpa16(sb + mat*8192u + (uint32_t)r*64u + ((uint32_t)(ldc ^ ((r >> 1) & 3)) << 4),
                  srcs[mat] + (size_t)r*K + k0 + ldc*8);
        }
        if (BN == 128){
#pragma unroll
            for (int i = 0; i < 4; i++){
                int r = ldr + (i & 1) * 64;
                int m = i >> 1;
                cpa16(sb + 16384u + m*8192u + (uint32_t)r*64u + ((uint32_t)(ldc ^ ((r >> 1) & 3)) << 4),
                      srcs[2 + m] + (size_t)r*K + k0 + ldc*8);
            }
        } else {
#pragma unroll
            for (int i = 0; i < 2; i++){
                int r = ldr;
                cpa16(sb + 16384u + i*(uint32_t)(BN*64) + (uint32_t)r*64u + ((uint32_t)(ldc ^ ((r >> 1) & 3)) << 4),
                      srcs[2 + i] + (size_t)r*K + k0 + ldc*8);
            }
        }
        cp_commit();
    };

    // ldmatrix lane geometry
    const int rA = (lane & 7) + ((lane >> 3) & 1) * 8;   // A row within 16
    const int cA = lane >> 4;                            // A k8-half 0/1
    const int jB = lane >> 3;                            // x4 matrix index
    const int ntOff = jB >> 1;                           // nt within pair
    const int cBn = jB & 1;                              // k8-half
    const int rBn = lane & 7;

    prefetch(0);
    prefetch(1);

    for (int ch = 0; ch < NC; ch++){
        if (ch + 1 < NC) cp_wait1(); else cp_wait0();
        __syncthreads();
        uint32_t sb  = smb + (uint32_t)(ch % 3) * STG;
        uint32_t sbB = sb + 16384u;

        uint32_t bh[4][2], bl[4][2];
        uint32_t ah[2][4], al[2][4];   // A frags for an mt PAIR

        auto loadB = [&](int kb){
#pragma unroll
            for (int p = 0; p < 2; p++){
                int nt = p*2 + ntOff;
                int row = wn + nt*8 + rBn;
                uint32_t off = (uint32_t)row*64u + ((uint32_t)((kb*2 + cBn) ^ ((row >> 1) & 3)) << 4);
                uint32_t t[4];
                ldm_x4(t, sbB + off);
                bh[p*2][0]=t[0]; bh[p*2][1]=t[1]; bh[p*2+1][0]=t[2]; bh[p*2+1][1]=t[3];
                ldm_x4(t, sbB + (uint32_t)(BN*64) + off);
                bl[p*2][0]=t[0]; bl[p*2][1]=t[1]; bl[p*2+1][0]=t[2]; bl[p*2+1][1]=t[3];
            }
        };
        auto loadApair = [&](int kb, int pr){
#pragma unroll
            for (int hh2 = 0; hh2 < 2; hh2++){
                int row = wm + (pr*2 + hh2)*16 + rA;
                uint32_t off = (uint32_t)row*64u + ((uint32_t)((kb*2 + cA) ^ ((row >> 1) & 3)) << 4);
                ldm_x4(ah[hh2], sb + off);
                ldm_x4(al[hh2], sb + 8192u + off);
            }
        };

        loadB(0);

#pragma unroll
        for (int kb = 0; kb < 2; kb++){
#pragma unroll
            for (int pr = 0; pr < NPR; pr++){
                loadApair(kb, pr);
#pragma unroll
                for (int h2 = 0; h2 < 2; h2++)
#pragma unroll
                for (int nt = 0; nt < 4; nt++) mma16816(acc[pr*2+h2][nt], ah[h2], bh[nt]);
                // prefetch repositioned: issue after first MMA burst, not in
                // the post-barrier LSU pileup window
                if (kb == 0 && pr == 0 && ch + 2 < NC) prefetch(ch + 2);
#pragma unroll
                for (int h2 = 0; h2 < 2; h2++)
#pragma unroll
                for (int nt = 0; nt < 4; nt++) mma16816(acc[pr*2+h2][nt], al[h2], bh[nt]);
#pragma unroll
                for (int h2 = 0; h2 < 2; h2++)
#pragma unroll
                for (int nt = 0; nt < 4; nt++) mma16816(acc[pr*2+h2][nt], ah[h2], bl[nt]);
                if (kb == 0 && pr == NPR - 1) loadB(1);
            }
        }
    }
    __syncthreads();

    float* Cz = C + (size_t)blockIdx.z * ((size_t)gridDim.y * 128) * N;

    // ------------------ epilogue ------------------
    if (MODE == 3){
        float* staps = (float*)sm;                 // [131][33]
        float* sbias = (float*)(sm + 17424);       // 128 floats
        const int d0g = bn >> 2;                   // 32 d-values per block
        for (int idx = tid; idx < 131*32; idx += 256){
            int i = idx >> 5, dd = idx & 31;
            int t = bm - 3 + i;
            float tv = 0.f;
            if (t >= 0){
                size_t gix = (size_t)t*CONV_DIM + d0g + dd;
                tv = __bfloat162float(tapsh[gix]) + __bfloat162float(tapsl[gix]);
            }
            staps[i*33 + dd] = tv;
        }
        if (tid < 128) sbias[tid] = bias[bn + tid];
        __syncthreads();
#pragma unroll
        for (int mt = 0; mt < MT; mt++)
#pragma unroll
        for (int nt = 0; nt < 4; nt++){
            int cb = wn + nt*8 + (lane & 3)*2;     // kernel-col
            int dd = (cb >> 2) & 31;               // local d
            int w0 = cb & 3;                       // 0 or 2
            float b0 = sbias[cb], b1 = sbias[cb + 1];
#pragma unroll
            for (int rr = 0; rr < 2; rr++){
                int r = wm + mt*16 + (lane >> 2) + rr*8;
                float k0 = acc[mt][nt][rr*2 + 0] + b0;
                float k1 = acc[mt][nt][rr*2 + 1] + b1;
                float part = staps[(r + w0)*33 + dd]*k0 + staps[(r + w0 + 1)*33 + dd]*k1;
                float oth = __shfl_xor_sync(0xffffffffu, part, 1);
                if ((lane & 1) == 0)
                    Cz[(size_t)(bm + r)*CONV_DIM + d0g + dd] = siluf(part + oth);
            }
        }
    } else {
#pragma unroll
        for (int mt = 0; mt < MT; mt++)
#pragma unroll
        for (int nt = 0; nt < 4; nt++){
            int cb = wn + nt*8 + (lane & 3)*2;
#pragma unroll
            for (int rr = 0; rr < 2; rr++){
                int r = bm + wm + mt*16 + (lane >> 2) + rr*8;
                float v0 = acc[mt][nt][rr*2 + 0], v1 = acc[mt][nt][rr*2 + 1];
                size_t idx = (size_t)r*N + bn + cb;
                if (MODE == 0) *(float2*)(Cz + idx) = make_float2(v0, v1);
                if (MODE == 1){
                    __nv_bfloat16 h0 = __float2bfloat16(v0), h1 = __float2bfloat16(v1);
                    *(__nv_bfloat162*)(Ch + idx) = __halves2bfloat162(h0, h1);
                    __nv_bfloat16 l0 = __float2bfloat16(v0 - __bfloat162float(h0));
                    __nv_bfloat16 l1 = __float2bfloat16(v1 - __bfloat162float(h1));
                    *(__nv_bfloat162*)(Cl + idx) = __halves2bfloat162(l0, l1);
                }
            }
        }
    }
}

// ---------------- merge split-K partials -> silu -> bf16 hi/lo --------------
__global__ __launch_bounds__(256)
void merge_h_kernel(const float* __restrict__ part,
                    __nv_bfloat16* __restrict__ hh, __nv_bfloat16* __restrict__ hl)
{
    const size_t P = (size_t)T_SEQ * GEN_HIDDEN;
    size_t i = ((size_t)blockIdx.x * 256 + threadIdx.x) * 4;
    float4 a = *(const float4*)(part + i);
    float4 b = *(const float4*)(part + P + i);
    float4 c = *(const float4*)(part + 2*P + i);
    float4 d = *(const float4*)(part + 3*P + i);
    float v[4] = { siluf(a.x+b.x+c.x+d.x), siluf(a.y+b.y+c.y+d.y),
                   siluf(a.z+b.z+c.z+d.z), siluf(a.w+b.w+c.w+d.w) };
#pragma unroll
    for (int j = 0; j < 4; j++){
        __nv_bfloat16 h0 = __float2bfloat16(v[j]);
        hh[i+j] = h0;
        hl[i+j] = __float2bfloat16(v[j] - __bfloat162float(h0));
    }
}

// ---------------- fp32 -> bf16 hi/lo split (row-major) ----------------------
__global__ __launch_bounds__(256)
void split4_kernel(const float* __restrict__ in, __nv_bfloat16* __restrict__ h,
                   __nv_bfloat16* __restrict__ l)
{
    int i = (blockIdx.x*256 + threadIdx.x)*4;
    float4 v = *(const float4*)(in + i);
    __nv_bfloat16 h0=__float2bfloat16(v.x), h1=__float2bfloat16(v.y),
                  h2=__float2bfloat16(v.z), h3=__float2bfloat16(v.w);
    h[i]=h0; h[i+1]=h1; h[i+2]=h2; h[i+3]=h3;
    l[i]  =__float2bfloat16(v.x-__bfloat162float(h0));
    l[i+1]=__float2bfloat16(v.y-__bfloat162float(h1));
    l[i+2]=__float2bfloat16(v.z-__bfloat162float(h2));
    l[i+3]=__float2bfloat16(v.w-__bfloat162float(h3));
}

// ---------------- fp32 [R,C] -> transposed bf16 hi/lo [C,R] v2 --------------
__global__ __launch_bounds__(256)
void transpose_split_kernel(const float* __restrict__ in, __nv_bfloat16* __restrict__ oh,
                            __nv_bfloat16* __restrict__ ol, int R, int C)
{
    __shared__ float t[64][65];
    const int tid = threadIdx.x;
    const int rb = blockIdx.y*64, cb = blockIdx.x*64;
    const int c4 = tid & 15;           // float4 col
    const int r0 = tid >> 4;           // 0..15
#pragma unroll
    for (int i = 0; i < 4; i++){
        int r = r0 + i*16;
        float4 v = *(const float4*)(in + (size_t)(rb+r)*C + cb + c4*4);
        t[r][c4*4+0]=v.x; t[r][c4*4+1]=v.y; t[r][c4*4+2]=v.z; t[r][c4*4+3]=v.w;
    }
    __syncthreads();
    const int rl = (tid & 31)*2;       // r pair
    const int cl0 = tid >> 5;          // 0..7
#pragma unroll
    for (int i = 0; i < 8; i++){
        int c = cl0 + i*8;
        float v0 = t[rl][c], v1 = t[rl+1][c];
        size_t idx = (size_t)(cb+c)*R + rb + rl;
        __nv_bfloat16 h0 = __float2bfloat16(v0), h1 = __float2bfloat16(v1);
        *(__nv_bfloat162*)(oh + idx) = __halves2bfloat162(h0, h1);
        __nv_bfloat16 l0 = __float2bfloat16(v0 - __bfloat162float(h0));
        __nv_bfloat16 l1 = __float2bfloat16(v1 - __bfloat162float(h1));
        *(__nv_bfloat162*)(ol + idx) = __halves2bfloat162(l0, l1);
    }
}

// ---------------- ba v2: smem-tiled GEMV, 32 rows/block ---------------------
__global__ __launch_bounds__(256)
void ba2_kernel(const float* __restrict__ x, const float* __restrict__ W_ba,
                float* __restrict__ beta, float* __restrict__ decay)
{
    __shared__ float sw[64][32];
    __shared__ float sx[32][64];
    const int tid = threadIdx.x, lane = tid & 31, w = tid >> 5;
    const int r0 = blockIdx.x * 32;

    float acc[4] = {0.f, 0.f, 0.f, 0.f};
    for (int k0 = 0; k0 < D_MODEL; k0 += 64){
        __syncthreads();
#pragma unroll
        for (int jj = 0; jj < 2; jj++){
            int i4 = tid + jj*256;
            { int row = i4 >> 3, cc = i4 & 7;
              *(float4*)&sw[row][cc*4] = *(const float4*)(W_ba + (size_t)(k0+row)*32 + cc*4); }
            { int row = i4 >> 4, cc = i4 & 15;
              *(float4*)&sx[row][cc*4] = *(const float4*)(x + (size_t)(r0+row)*D_MODEL + k0 + cc*4); }
        }
        __syncthreads();
#pragma unroll 16
        for (int kk = 0; kk < 64; kk++){
            float wv = sw[kk][lane];
#pragma unroll
            for (int rr = 0; rr < 4; rr++)
                acc[rr] = fmaf(sx[w*4 + rr][kk], wv, acc[rr]);
        }
    }
#pragma unroll
    for (int rr = 0; rr < 4; rr++){
        int t = r0 + w*4 + rr;
        if (lane < 16) beta[t*NH + lane]         = 1.0f / (1.0f + expf(-acc[rr]));
        else           decay[t*NH + (lane - 16)] = 1.0f / (1.0f + expf( acc[rr]));
    }
}

// ---------------- per-(t,h) l2norm scales for q,k ---------------------------
__global__ __launch_bounds__(256)
void scale_kernel(const float* __restrict__ u, float* __restrict__ qs, float* __restrict__ ks)
{
    int gt = blockIdx.x * blockDim.x + threadIdx.x;
    int w = gt >> 5, lane = gt & 31;
    int t = w >> 4, h = w & 15;
    const float* base = u + (size_t)t*CONV_DIM + h*128;
    float4 a = *(const float4*)(base + lane*4);
    float sq = a.x*a.x + a.y*a.y + a.z*a.z + a.w*a.w;
    float4 b = *(const float4*)(base + 2048 + lane*4);
    float sk = b.x*b.x + b.y*b.y + b.z*b.z + b.w*b.w;
#pragma unroll
    for (int m = 16; m >= 1; m >>= 1) {
        sq += __shfl_xor_sync(0xffffffffu, sq, m);
        sk += __shfl_xor_sync(0xffffffffu, sk, m);
    }
    if (lane == 0) {
        qs[t*NH + h] = rsqrtf(sq + 1e-6f) * 0.08838834764831845f;
        ks[t*NH + h] = rsqrtf(sk + 1e-6f);
    }
}

// ---------------- gated delta-rule scan v2 (R12 proven) ---------------------
#define CH 8
#define NCH (T_SEQ/CH)

__global__ __launch_bounds__(128)
void scan_kernel(const float* __restrict__ u,
                 const float* __restrict__ ksc_g, const float* __restrict__ qsc_g,
                 const float* __restrict__ beta_g, const float* __restrict__ decay_g,
                 __nv_bfloat16* __restrict__ oh, __nv_bfloat16* __restrict__ ol)
{
    __shared__ float sk[2][CH][128];
    __shared__ float sq[2][CH][128];
    __shared__ float sv[2][CH][8];
    __shared__ float ss[2][CH][4];

    const int tid = threadIdx.x, lane = tid & 31, warp = tid >> 5;
    const int h = blockIdx.y, vg = blockIdx.x;
    const int cw = lane >> 4;
    const int kg = lane & 15;
    const int col_local = warp*2 + cw;
    const int v = vg*8 + col_local;

    float s[8];
#pragma unroll
    for (int i=0;i<8;i++) s[i] = 0.f;

    auto prefetch = [&](int c, int b){
        int t0 = c*CH;
#pragma unroll
        for (int j2=0;j2<2;j2++){
            int idx = tid + j2*128;
            int st = idx >> 5, f4 = idx & 31;
            const float* rowbase = u + (size_t)(t0+st)*CONV_DIM + h*128 + f4*4;
            cpa16(smem_u32(&sq[b][st][f4*4]), rowbase);
            cpa16(smem_u32(&sk[b][st][f4*4]), rowbase + 2048);
        }
        if (tid < 16){
            int st = tid >> 1, f4 = tid & 1;
            cpa16(smem_u32(&sv[b][st][f4*4]),
                  u + (size_t)(t0+st)*CONV_DIM + 4096 + h*128 + vg*8 + f4*4);
        } else if (tid < 48){
            int r = tid - 16;
            int st = r & 7, wh = r >> 3;
            const float* src = (wh==0) ? ksc_g : (wh==1) ? qsc_g : (wh==2) ? beta_g : decay_g;
            cpa4(&ss[b][st][wh], src + (t0+st)*NH + h);
        }
    };

    prefetch(0, 0);
    cp_commit();

    for (int c = 0; c < NCH; c++){
        int b = c & 1;
        if (c+1 < NCH){
            prefetch(c+1, b^1);
            cp_commit();
            cp_wait1();
        } else {
            cp_wait0();
        }
        __syncthreads();

#pragma unroll
        for (int j = 0; j < CH; j++){
            float ksc = ss[b][j][0], qsc = ss[b][j][1];
            float bet = ss[b][j][2], eg  = ss[b][j][3];
            float vv  = sv[b][j][col_local];

            float kf[8], qf[8];
            *(float4*)&kf[0] = *(const float4*)&sk[b][j][kg*4];
            *(float4*)&kf[4] = *(const float4*)&sk[b][j][64 + kg*4];
            *(float4*)&qf[0] = *(const float4*)&sq[b][j][kg*4];
            *(float4*)&qf[4] = *(const float4*)&sq[b][j][64 + kg*4];

            float a0=0.f, a1=0.f;
#pragma unroll
            for (int i=0;i<8;i+=2){ a0 = fmaf(kf[i], s[i], a0); a1 = fmaf(kf[i+1], s[i+1], a1); }
            float dot = a0 + a1;
            dot += __shfl_xor_sync(0xffffffffu, dot, 1);
            dot += __shfl_xor_sync(0xffffffffu, dot, 2);
            dot += __shfl_xor_sync(0xffffffffu, dot, 4);
            dot += __shfl_xor_sync(0xffffffffu, dot, 8);
            float pred = dot * ksc * eg;
            float uk = bet * (vv - pred) * ksc;
#pragma unroll
            for (int i=0;i<8;i++) s[i] = fmaf(eg, s[i], kf[i]*uk);
            float c0=0.f, c1=0.f;
#pragma unroll
            for (int i=0;i<8;i+=2){ c0 = fmaf(qf[i], s[i], c0); c1 = fmaf(qf[i+1], s[i+1], c1); }
            float od = c0 + c1;
            od += __shfl_xor_sync(0xffffffffu, od, 1);
            od += __shfl_xor_sync(0xffffffffu, od, 2);
            od += __shfl_xor_sync(0xffffffffu, od, 4);
            od += __shfl_xor_sync(0xffffffffu, od, 8);
            if (kg == 0){
                int t = c*CH + j;
                float ov = od * qsc;
                size_t idx = (size_t)t*(NH*128) + h*128 + v;
                __nv_bfloat16 h0 = __float2bfloat16(ov);
                oh[idx] = h0;
                ol[idx] = __float2bfloat16(ov - __bfloat162float(h0));
            }
        }
        __syncthreads();
    }
}

// ---------------- launch ----------------------------------------------------
#define DSMEM_128 (3*(16384 + 128*128))   // 98304
#define DSMEM_64  (3*(16384 + 64*128))    // 73728

extern "C" void kernel_launch(void* const* d_in, const int* in_sizes, int n_in,
                              void* d_out, int out_size)
{
    const float* x      = (const float*)d_in[0];
    const float* W_qkv  = (const float*)d_in[1];
    const float* W_ba   = (const float*)d_in[2];
    const float* gen_w1 = (const float*)d_in[3];
    const float* gen_w2 = (const float*)d_in[4];
    const float* gen_b2 = (const float*)d_in[5];
    const float* W_o    = (const float*)d_in[6];
    float* y = (float*)d_out;

    float *u, *hpart, *beta, *decay, *qs, *ks;
    cudaGetSymbolAddress((void**)&u,     g_u);
    cudaGetSymbolAddress((void**)&hpart, g_hpart);
    cudaGetSymbolAddress((void**)&beta,  g_beta);
    cudaGetSymbolAddress((void**)&decay, g_decay);
    cudaGetSymbolAddress((void**)&qs,    g_qs);
    cudaGetSymbolAddress((void**)&ks,    g_ks);
    __nv_bfloat16 *xh,*xl,*qkvh,*qkvl,*hh,*hl,*oh,*ol;
    __nv_bfloat16 *wqkvh,*wqkvl,*w1h,*w1l,*w2h,*w2l,*woh,*wol;
    cudaGetSymbolAddress((void**)&xh, g_xh);     cudaGetSymbolAddress((void**)&xl, g_xl);
    cudaGetSymbolAddress((void**)&qkvh, g_qkvh); cudaGetSymbolAddress((void**)&qkvl, g_qkvl);
    cudaGetSymbolAddress((void**)&hh, g_hh);     cudaGetSymbolAddress((void**)&hl, g_hl);
    cudaGetSymbolAddress((void**)&oh, g_oh);     cudaGetSymbolAddress((void**)&ol, g_ol);
    cudaGetSymbolAddress((void**)&wqkvh, g_wqkvh); cudaGetSymbolAddress((void**)&wqkvl, g_wqkvl);
    cudaGetSymbolAddress((void**)&w1h, g_w1h);   cudaGetSymbolAddress((void**)&w1l, g_w1l);
    cudaGetSymbolAddress((void**)&w2h, g_w2h);   cudaGetSymbolAddress((void**)&w2l, g_w2l);
    cudaGetSymbolAddress((void**)&woh, g_woh);   cudaGetSymbolAddress((void**)&wol, g_wol);

    cudaFuncSetAttribute((const void*)mma_gemm<0,128>, cudaFuncAttributeMaxDynamicSharedMemorySize, DSMEM_128);
    cudaFuncSetAttribute((const void*)mma_gemm<1,128>, cudaFuncAttributeMaxDynamicSharedMemorySize, DSMEM_128);
    cudaFuncSetAttribute((const void*)mma_gemm<0,64>,  cudaFuncAttributeMaxDynamicSharedMemorySize, DSMEM_64);
    cudaFuncSetAttribute((const void*)mma_gemm<3,128>, cudaFuncAttributeMaxDynamicSharedMemorySize, DSMEM_128);

    // Launch order: ncu captures launch #4 -> keep qkv GEMM there.
    // 1) W_qkv transpose+split
    transpose_split_kernel<<<dim3(CONV_DIM/64, D_MODEL/64), 256>>>(W_qkv, wqkvh, wqkvl, D_MODEL, CONV_DIM);
    // 2) x split
    split4_kernel<<<(T_SEQ*D_MODEL)/1024, 256>>>(x, xh, xl);
    // 3) beta/decay
    ba2_kernel<<<T_SEQ/32, 256>>>(x, W_ba, beta, decay);
    // 4) qkv = x @ W_qkv -> bf16 hi/lo only  <-- ncu capture target
    mma_gemm<1,128><<<dim3(CONV_DIM/128, T_SEQ/128), 256, DSMEM_128>>>(
        xh, xl, wqkvh, wqkvl, CONV_DIM, D_MODEL, D_MODEL, nullptr, qkvh, qkvl, nullptr, nullptr, nullptr);
    // 5) gen_w1 transpose+split
    transpose_split_kernel<<<dim3(GEN_HIDDEN/64, CONV_DIM/64), 256>>>(gen_w1, w1h, w1l, CONV_DIM, GEN_HIDDEN);
    // 6) gen_w2 transpose+split
    transpose_split_kernel<<<dim3(KERN_N/64, GEN_HIDDEN/64), 256>>>(gen_w2, w2h, w2l, GEN_HIDDEN, KERN_N);
    // 7) h partials: split-K=4 over K=6144
    mma_gemm<0,64><<<dim3(GEN_HIDDEN/64, T_SEQ/128, 4), 256, DSMEM_64>>>(
        qkvh, qkvl, w1h, w1l, GEN_HIDDEN, CONV_DIM, CONV_DIM/4, hpart, nullptr, nullptr, nullptr, nullptr, nullptr);
    // 8) merge partials -> silu -> hh/hl
    merge_h_kernel<<<(T_SEQ*GEN_HIDDEN)/1024, 256>>>(hpart, hh, hl);
    // 9) u = silu(conv(qkv, h @ gen_w2 + b2)); taps from bf16 hi/lo qkv
    mma_gemm<3,128><<<dim3(KERN_N/128, T_SEQ/128), 256, DSMEM_128>>>(
        hh, hl, w2h, w2l, KERN_N, GEN_HIDDEN, GEN_HIDDEN, u, nullptr, nullptr, qkvh, qkvl, gen_b2);
    // 10) scales
    scale_kernel<<<(T_SEQ*NH*32)/256, 256>>>(u, qs, ks);
    // 11) scan -> oh/ol bf16 directly
    scan_kernel<<<dim3(16, NH), 128>>>(u, ks, qs, beta, decay, oh, ol);
    // 12) W_o transpose+split
    transpose_split_kernel<<<dim3(D_MODEL/64, D_MODEL/64), 256>>>(W_o, woh, wol, D_MODEL, D_MODEL);
    // 13) y = o @ W_o
    mma_gemm<0,64><<<dim3(D_MODEL/64, T_SEQ/128), 256, DSMEM_64>>>(
        oh, ol, woh, wol, D_MODEL, D_MODEL, D_MODEL, y, nullptr, nullptr, nullptr, nullptr, nullptr);
}